// round 1
// baseline (speedup 1.0000x reference)
#include <cuda_runtime.h>
#include <cstddef>

#define NNODES 100000
#define EDGES  1600000
#define HDIM   128

// ---------------- scratch (device globals; no allocation in kernel_launch) ----
__device__ __align__(256) float g_hp_ppi[(size_t)NNODES * HDIM];
__device__ __align__(256) float g_hp_sim[(size_t)NNODES * HDIM];
__device__ __align__(256) float g_acc   [(size_t)NNODES * HDIM];
__device__ __align__(256) float g_h     [(size_t)NNODES * HDIM];
__device__ __align__(256) float g_coef_ppi[EDGES];
__device__ __align__(256) float g_coef_sim[EDGES];
__device__ __align__(256) float g_deg[4 * NNODES];   // [out_ppi | in_ppi | out_sim | in_sim]

// ---------------- kernels ----------------------------------------------------

__global__ void zero_kernel(float4* __restrict__ p, int n4) {
    int i = blockIdx.x * blockDim.x + threadIdx.x;
    if (i < n4) p[i] = make_float4(0.f, 0.f, 0.f, 0.f);
}

__global__ void deg_kernel(const int* __restrict__ src, const int* __restrict__ dst,
                           float* __restrict__ deg_out, float* __restrict__ deg_in, int e) {
    int i = blockIdx.x * blockDim.x + threadIdx.x;
    if (i < e) {
        atomicAdd(&deg_out[src[i]], 1.0f);
        atomicAdd(&deg_in[dst[i]], 1.0f);
    }
}

__global__ void coef_kernel(const int* __restrict__ src, const int* __restrict__ dst,
                            const float* __restrict__ deg_out, const float* __restrict__ deg_in,
                            float* __restrict__ coef, int e) {
    int i = blockIdx.x * blockDim.x + threadIdx.x;
    if (i < e) {
        float a = rsqrtf(fmaxf(deg_out[src[i]], 1.0f));
        float b = rsqrtf(fmaxf(deg_in[dst[i]], 1.0f));
        coef[i] = a * b;
    }
}

// Y[:, colbase:colbase+64] = X @ W[:, colbase:colbase+64]
// warp-per-row; W column-half cached in 32KB static smem; blockIdx.y selects half.
__global__ void gemm128_kernel(const float* __restrict__ X, const float* __restrict__ W,
                               float* __restrict__ Y, int nrows) {
    __shared__ float Ws[HDIM][64];
    const int colbase = blockIdx.y * 64;
    for (int i = threadIdx.x; i < HDIM * 64; i += blockDim.x) {
        int k = i >> 6, c = i & 63;
        Ws[k][c] = W[k * HDIM + colbase + c];
    }
    __syncthreads();

    const int warp = threadIdx.x >> 5;
    const int lane = threadIdx.x & 31;
    const int wpb = blockDim.x >> 5;

    for (int row = blockIdx.x * wpb + warp; row < nrows; row += gridDim.x * wpb) {
        const float* x = X + (size_t)row * HDIM;
        float a0 = 0.f, a1 = 0.f;
#pragma unroll
        for (int ch = 0; ch < 4; ch++) {
            float xv = x[ch * 32 + lane];
#pragma unroll
            for (int kk = 0; kk < 32; kk++) {
                float xk = __shfl_sync(0xffffffffu, xv, kk);
                float2 w = *(const float2*)&Ws[ch * 32 + kk][lane * 2];
                a0 += xk * w.x;
                a1 += xk * w.y;
            }
        }
        *(float2*)&Y[(size_t)row * HDIM + colbase + lane * 2] = make_float2(a0, a1);
    }
}

// warp-per-edge: acc[dst] += coef * hp[src]  (vectorized L2 reduction, 1 float4/lane)
__global__ void edge_scatter_kernel(const float* __restrict__ hp,
                                    const int* __restrict__ src, const int* __restrict__ dst,
                                    const float* __restrict__ coef,
                                    float* __restrict__ acc, int e) {
    int w = (blockIdx.x * blockDim.x + threadIdx.x) >> 5;
    int lane = threadIdx.x & 31;
    if (w >= e) return;
    int s = src[w];
    int d = dst[w];
    float c = coef[w];
    float4 v = ((const float4*)(hp + (size_t)s * HDIM))[lane];
    v.x *= c; v.y *= c; v.z *= c; v.w *= c;
    float4* out = ((float4*)(acc + (size_t)d * HDIM)) + lane;
    asm volatile("red.global.add.v4.f32 [%0], {%1,%2,%3,%4};"
                 :: "l"(out), "f"(v.x), "f"(v.y), "f"(v.z), "f"(v.w)
                 : "memory");
}

// out = relu(0.5*acc + 0.5*(bp+bs)), elementwise over [N,128]
__global__ void finalize_kernel(const float* __restrict__ acc,
                                const float* __restrict__ bp, const float* __restrict__ bs,
                                float* __restrict__ out, int total) {
    int i = blockIdx.x * blockDim.x + threadIdx.x;
    int idx = i * 4;
    if (idx < total) {
        float4 a = *(const float4*)(acc + idx);
        int c = idx & (HDIM - 1);
        float b0 = 0.5f * (bp[c] + bs[c]);
        float b1 = 0.5f * (bp[c + 1] + bs[c + 1]);
        float b2 = 0.5f * (bp[c + 2] + bs[c + 2]);
        float b3 = 0.5f * (bp[c + 3] + bs[c + 3]);
        float4 r;
        r.x = fmaxf(0.5f * a.x + b0, 0.f);
        r.y = fmaxf(0.5f * a.y + b1, 0.f);
        r.z = fmaxf(0.5f * a.z + b2, 0.f);
        r.w = fmaxf(0.5f * a.w + b3, 0.f);
        *(float4*)(out + idx) = r;
    }
}

// warp-per-pair: logits[p] = [z[s] ; z[d]] @ Wc + bc   (Wc row-major [256,2])
__global__ void pair_kernel(const float* __restrict__ z,
                            const int* __restrict__ ps, const int* __restrict__ pd,
                            const float* __restrict__ Wc, const float* __restrict__ bc,
                            float* __restrict__ out, int p) {
    int w = (blockIdx.x * blockDim.x + threadIdx.x) >> 5;
    int lane = threadIdx.x & 31;
    if (w >= p) return;
    int s = ps[w];
    int d = pd[w];
    float4 zs = ((const float4*)(z + (size_t)s * HDIM))[lane];
    float4 zd = ((const float4*)(z + (size_t)d * HDIM))[lane];
    const float4* wc4 = (const float4*)Wc;
    // rows lane*4 .. lane*4+3 for the src half
    float4 wa = wc4[lane * 2];      // {W[k][0],W[k][1],W[k+1][0],W[k+1][1]}
    float4 wb = wc4[lane * 2 + 1];  // rows k+2, k+3
    float l0 = zs.x * wa.x + zs.y * wa.z + zs.z * wb.x + zs.w * wb.z;
    float l1 = zs.x * wa.y + zs.y * wa.w + zs.z * wb.y + zs.w * wb.w;
    // rows 128+lane*4 .. for the dst half
    float4 wcv = wc4[64 + lane * 2];
    float4 wd  = wc4[64 + lane * 2 + 1];
    l0 += zd.x * wcv.x + zd.y * wcv.z + zd.z * wd.x + zd.w * wd.z;
    l1 += zd.x * wcv.y + zd.y * wcv.w + zd.z * wd.y + zd.w * wd.w;
#pragma unroll
    for (int o = 16; o; o >>= 1) {
        l0 += __shfl_xor_sync(0xffffffffu, l0, o);
        l1 += __shfl_xor_sync(0xffffffffu, l1, o);
    }
    if (lane == 0) {
        out[(size_t)w * 2]     = l0 + bc[0];
        out[(size_t)w * 2 + 1] = l1 + bc[1];
    }
}

// ---------------- launch -----------------------------------------------------

extern "C" void kernel_launch(void* const* d_in, const int* in_sizes, int n_in,
                              void* d_out, int out_size) {
    const float* feat    = (const float*)d_in[0];
    const int* src_ppi   = (const int*)d_in[1];
    const int* dst_ppi   = (const int*)d_in[2];
    const int* src_sim   = (const int*)d_in[3];
    const int* dst_sim   = (const int*)d_in[4];
    const int* pair_src  = (const int*)d_in[5];
    const int* pair_dst  = (const int*)d_in[6];
    const float* W0_ppi  = (const float*)d_in[7];
    const float* b0_ppi  = (const float*)d_in[8];
    const float* W0_sim  = (const float*)d_in[9];
    const float* b0_sim  = (const float*)d_in[10];
    const float* W1_ppi  = (const float*)d_in[11];
    const float* b1_ppi  = (const float*)d_in[12];
    const float* W1_sim  = (const float*)d_in[13];
    const float* b1_sim  = (const float*)d_in[14];
    const float* Wc      = (const float*)d_in[15];
    const float* bc      = (const float*)d_in[16];

    const int n = in_sizes[0] / HDIM;   // 100000
    const int e = in_sizes[1];          // 1600000
    const int p = in_sizes[5];          // 200000

    float* zout   = (float*)d_out;                       // [n,128]
    float* logits = (float*)d_out + (size_t)n * HDIM;    // [p,2]

    float *hp_ppi, *hp_sim, *acc, *hbuf, *coef_ppi, *coef_sim, *deg;
    cudaGetSymbolAddress((void**)&hp_ppi,   g_hp_ppi);
    cudaGetSymbolAddress((void**)&hp_sim,   g_hp_sim);
    cudaGetSymbolAddress((void**)&acc,      g_acc);
    cudaGetSymbolAddress((void**)&hbuf,     g_h);
    cudaGetSymbolAddress((void**)&coef_ppi, g_coef_ppi);
    cudaGetSymbolAddress((void**)&coef_sim, g_coef_sim);
    cudaGetSymbolAddress((void**)&deg,      g_deg);

    const int TB = 256;
    const int nh = n * HDIM;
    const int zero_deg_blocks = (4 * n / 4 + TB - 1) / TB;
    const int zero_acc_blocks = (nh / 4 + TB - 1) / TB;
    const int e_blocks  = (e + TB - 1) / TB;
    const int sc_blocks = (int)(((long long)e * 32 + TB - 1) / TB);
    const int fin_blocks = (nh / 4 + TB - 1) / TB;
    const int pair_blocks = (int)(((long long)p * 32 + TB - 1) / TB);
    dim3 gemm_grid((n + 7) / 8, 2);

    // degrees + edge normalization coefs (shared by both layers)
    zero_kernel<<<zero_deg_blocks, TB>>>((float4*)deg, 4 * n / 4);
    deg_kernel<<<e_blocks, TB>>>(src_ppi, dst_ppi, deg, deg + n, e);
    deg_kernel<<<e_blocks, TB>>>(src_sim, dst_sim, deg + 2 * n, deg + 3 * n, e);
    coef_kernel<<<e_blocks, TB>>>(src_ppi, dst_ppi, deg, deg + n, coef_ppi, e);
    coef_kernel<<<e_blocks, TB>>>(src_sim, dst_sim, deg + 2 * n, deg + 3 * n, coef_sim, e);

    // ---- layer 0 ----
    gemm128_kernel<<<gemm_grid, TB>>>(feat, W0_ppi, hp_ppi, n);
    gemm128_kernel<<<gemm_grid, TB>>>(feat, W0_sim, hp_sim, n);
    zero_kernel<<<zero_acc_blocks, TB>>>((float4*)acc, nh / 4);
    edge_scatter_kernel<<<sc_blocks, TB>>>(hp_ppi, src_ppi, dst_ppi, coef_ppi, acc, e);
    edge_scatter_kernel<<<sc_blocks, TB>>>(hp_sim, src_sim, dst_sim, coef_sim, acc, e);
    finalize_kernel<<<fin_blocks, TB>>>(acc, b0_ppi, b0_sim, hbuf, nh);

    // ---- layer 1 ----
    gemm128_kernel<<<gemm_grid, TB>>>(hbuf, W1_ppi, hp_ppi, n);
    gemm128_kernel<<<gemm_grid, TB>>>(hbuf, W1_sim, hp_sim, n);
    zero_kernel<<<zero_acc_blocks, TB>>>((float4*)acc, nh / 4);
    edge_scatter_kernel<<<sc_blocks, TB>>>(hp_ppi, src_ppi, dst_ppi, coef_ppi, acc, e);
    edge_scatter_kernel<<<sc_blocks, TB>>>(hp_sim, src_sim, dst_sim, coef_sim, acc, e);
    finalize_kernel<<<fin_blocks, TB>>>(acc, b1_ppi, b1_sim, zout, nh);

    // ---- pair classifier ----
    pair_kernel<<<pair_blocks, TB>>>(zout, pair_src, pair_dst, Wc, bc, logits, p);
}

// round 2
// speedup vs baseline: 1.2078x; 1.2078x over previous
#include <cuda_runtime.h>
#include <cstddef>

#define NNODES 100000
#define EDGES  1600000
#define HDIM   128
#define SCAN_CHUNK 512
#define NBLK  ((NNODES + SCAN_CHUNK - 1) / SCAN_CHUNK)   // 196

// ---------------- scratch (device globals) -----------------------------------
__device__ __align__(256) float g_hp_ppi[(size_t)NNODES * HDIM];
__device__ __align__(256) float g_hp_sim[(size_t)NNODES * HDIM];
__device__ __align__(256) float g_h     [(size_t)NNODES * HDIM];
__device__ __align__(256) int2  g_edges_p[EDGES];   // {src, coef bits} sorted by dst
__device__ __align__(256) int2  g_edges_s[EDGES];
// [deg_out_p | deg_in_p | deg_out_s | deg_in_s | cursor_p | cursor_s] (6N)
__device__ __align__(256) int   g_ints[6 * NNODES];
__device__ __align__(256) int   g_offs[2 * NNODES]; // exclusive scan of deg_in per rel
__device__ __align__(256) int   g_partial[2 * 256];

// ---------------- kernels ----------------------------------------------------

__global__ void zero_i4_kernel(int4* __restrict__ p, int n4) {
    int i = blockIdx.x * blockDim.x + threadIdx.x;
    if (i < n4) p[i] = make_int4(0, 0, 0, 0);
}

__global__ void deg_kernel(const int* __restrict__ src, const int* __restrict__ dst,
                           int* __restrict__ deg_out, int* __restrict__ deg_in, int e) {
    int i = blockIdx.x * blockDim.x + threadIdx.x;
    if (i < e) {
        atomicAdd(&deg_out[src[i]], 1);
        atomicAdd(&deg_in[dst[i]], 1);
    }
}

// grid (NBLK, 2): per-chunk sums of deg_in
__global__ void partial_kernel(const int* __restrict__ din0, const int* __restrict__ din1,
                               int* __restrict__ partial, int n) {
    const int* din = blockIdx.y ? din1 : din0;
    int i = blockIdx.x * SCAN_CHUNK + threadIdx.x;
    int v = (i < n) ? din[i] : 0;
#pragma unroll
    for (int o = 16; o; o >>= 1) v += __shfl_xor_sync(0xffffffffu, v, o);
    __shared__ int ws[16];
    int lane = threadIdx.x & 31, wid = threadIdx.x >> 5;
    if (lane == 0) ws[wid] = v;
    __syncthreads();
    if (threadIdx.x == 0) {
        int s = 0;
#pragma unroll
        for (int k = 0; k < SCAN_CHUNK / 32; k++) s += ws[k];
        partial[blockIdx.y * 256 + blockIdx.x] = s;
    }
}

// 1 block, 512 threads: in-place exclusive scan of both relations' partials
__global__ void scan_partial_kernel(int* __restrict__ partial) {
    __shared__ int buf[2][256];
    int r = threadIdx.x >> 8, idx = threadIdx.x & 255;
    buf[r][idx] = (idx < NBLK) ? partial[r * 256 + idx] : 0;
    __syncthreads();
    for (int o = 1; o < 256; o <<= 1) {
        int v = (idx >= o) ? buf[r][idx - o] : 0;
        __syncthreads();
        buf[r][idx] += v;
        __syncthreads();
    }
    partial[r * 256 + idx] = idx ? buf[r][idx - 1] : 0;   // exclusive
}

// grid (NBLK, 2): block-exclusive scan of chunk + base -> offs
__global__ void scan_chunks_kernel(const int* __restrict__ din0, const int* __restrict__ din1,
                                   const int* __restrict__ partial, int* __restrict__ offs, int n) {
    const int* din = blockIdx.y ? din1 : din0;
    int i = blockIdx.x * SCAN_CHUNK + threadIdx.x;
    int val = (i < n) ? din[i] : 0;
    int lane = threadIdx.x & 31, wid = threadIdx.x >> 5;
    int incl = val;
#pragma unroll
    for (int o = 1; o < 32; o <<= 1) {
        int t = __shfl_up_sync(0xffffffffu, incl, o);
        if (lane >= o) incl += t;
    }
    __shared__ int ws[16];
    if (lane == 31) ws[wid] = incl;
    __syncthreads();
    if (wid == 0 && lane < 16) {
        int v = ws[lane];
#pragma unroll
        for (int o = 1; o < 16; o <<= 1) {
            int t = __shfl_up_sync(0x0000ffffu, v, o);
            if (lane >= o) v += t;
        }
        ws[lane] = v;
    }
    __syncthreads();
    int base = (wid ? ws[wid - 1] : 0) + partial[blockIdx.y * 256 + blockIdx.x];
    if (i < n) offs[blockIdx.y * NNODES + i] = base + incl - val;
}

// slot-scatter: edges[offs[dst] + cursor[dst]++] = {src, coef}
__global__ void sort_kernel(const int* __restrict__ src, const int* __restrict__ dst,
                            const int* __restrict__ deg_out, const int* __restrict__ deg_in,
                            const int* __restrict__ offs, int* __restrict__ cursor,
                            int2* __restrict__ edges, int e) {
    int i = blockIdx.x * blockDim.x + threadIdx.x;
    if (i >= e) return;
    int s = src[i], d = dst[i];
    float c = rsqrtf(fmaxf((float)deg_out[s], 1.0f)) * rsqrtf(fmaxf((float)deg_in[d], 1.0f));
    int slot = offs[d] + atomicAdd(&cursor[d], 1);
    edges[slot] = make_int2(s, __float_as_int(c));
}

// Y[:, colbase:colbase+64] = X @ W[:, colbase:colbase+64]; warp-per-row
__global__ void gemm128_kernel(const float* __restrict__ X, const float* __restrict__ W,
                               float* __restrict__ Y, int nrows) {
    __shared__ float Ws[HDIM][64];
    const int colbase = blockIdx.y * 64;
    for (int i = threadIdx.x; i < HDIM * 64; i += blockDim.x) {
        int k = i >> 6, c = i & 63;
        Ws[k][c] = W[k * HDIM + colbase + c];
    }
    __syncthreads();
    const int warp = threadIdx.x >> 5, lane = threadIdx.x & 31, wpb = blockDim.x >> 5;
    for (int row = blockIdx.x * wpb + warp; row < nrows; row += gridDim.x * wpb) {
        const float* x = X + (size_t)row * HDIM;
        float a0 = 0.f, a1 = 0.f;
#pragma unroll
        for (int ch = 0; ch < 4; ch++) {
            float xv = x[ch * 32 + lane];
#pragma unroll
            for (int kk = 0; kk < 32; kk++) {
                float xk = __shfl_sync(0xffffffffu, xv, kk);
                float2 w = *(const float2*)&Ws[ch * 32 + kk][lane * 2];
                a0 += xk * w.x;
                a1 += xk * w.y;
            }
        }
        *(float2*)&Y[(size_t)row * HDIM + colbase + lane * 2] = make_float2(a0, a1);
    }
}

// warp-per-node: v = sum over both relations' in-edges of coef*hp[src];
// out = relu(0.5*(v + bp + bs))
__global__ void aggregate_kernel(const float* __restrict__ hp_p, const float* __restrict__ hp_s,
                                 const int2* __restrict__ ep, const int* __restrict__ offs_p,
                                 const int* __restrict__ deg_p,
                                 const int2* __restrict__ es, const int* __restrict__ offs_s,
                                 const int* __restrict__ deg_s,
                                 const float* __restrict__ bp, const float* __restrict__ bs,
                                 float* __restrict__ out, int n) {
    int w = (blockIdx.x * blockDim.x + threadIdx.x) >> 5;
    int lane = threadIdx.x & 31;
    if (w >= n) return;
    float4 v = make_float4(0.f, 0.f, 0.f, 0.f);

#pragma unroll 1
    for (int rel = 0; rel < 2; rel++) {
        const int2* ed = rel ? es : ep;
        const float* hp = rel ? hp_s : hp_p;
        int st = rel ? offs_s[w] : offs_p[w];
        int en = st + (rel ? deg_s[w] : deg_p[w]);
        int j = st;
        for (; j + 1 < en; j += 2) {
            int2 e0 = __ldg(&ed[j]);
            int2 e1 = __ldg(&ed[j + 1]);
            float4 h0 = __ldg((const float4*)(hp + (size_t)e0.x * HDIM) + lane);
            float4 h1 = __ldg((const float4*)(hp + (size_t)e1.x * HDIM) + lane);
            float c0 = __int_as_float(e0.y), c1 = __int_as_float(e1.y);
            v.x += c0 * h0.x; v.y += c0 * h0.y; v.z += c0 * h0.z; v.w += c0 * h0.w;
            v.x += c1 * h1.x; v.y += c1 * h1.y; v.z += c1 * h1.z; v.w += c1 * h1.w;
        }
        if (j < en) {
            int2 e0 = __ldg(&ed[j]);
            float4 h0 = __ldg((const float4*)(hp + (size_t)e0.x * HDIM) + lane);
            float c0 = __int_as_float(e0.y);
            v.x += c0 * h0.x; v.y += c0 * h0.y; v.z += c0 * h0.z; v.w += c0 * h0.w;
        }
    }
    float4 b1 = ((const float4*)bp)[lane];
    float4 b2 = ((const float4*)bs)[lane];
    float4 r;
    r.x = fmaxf(0.5f * (v.x + b1.x + b2.x), 0.f);
    r.y = fmaxf(0.5f * (v.y + b1.y + b2.y), 0.f);
    r.z = fmaxf(0.5f * (v.z + b1.z + b2.z), 0.f);
    r.w = fmaxf(0.5f * (v.w + b1.w + b2.w), 0.f);
    *((float4*)(out + (size_t)w * HDIM) + lane) = r;
}

// warp-per-pair classifier
__global__ void pair_kernel(const float* __restrict__ z,
                            const int* __restrict__ ps, const int* __restrict__ pd,
                            const float* __restrict__ Wc, const float* __restrict__ bc,
                            float* __restrict__ out, int p) {
    int w = (blockIdx.x * blockDim.x + threadIdx.x) >> 5;
    int lane = threadIdx.x & 31;
    if (w >= p) return;
    int s = ps[w], d = pd[w];
    float4 zs = ((const float4*)(z + (size_t)s * HDIM))[lane];
    float4 zd = ((const float4*)(z + (size_t)d * HDIM))[lane];
    const float4* wc4 = (const float4*)Wc;
    float4 wa = wc4[lane * 2], wb = wc4[lane * 2 + 1];
    float l0 = zs.x * wa.x + zs.y * wa.z + zs.z * wb.x + zs.w * wb.z;
    float l1 = zs.x * wa.y + zs.y * wa.w + zs.z * wb.y + zs.w * wb.w;
    float4 wcv = wc4[64 + lane * 2], wd = wc4[64 + lane * 2 + 1];
    l0 += zd.x * wcv.x + zd.y * wcv.z + zd.z * wd.x + zd.w * wd.z;
    l1 += zd.x * wcv.y + zd.y * wcv.w + zd.z * wd.y + zd.w * wd.w;
#pragma unroll
    for (int o = 16; o; o >>= 1) {
        l0 += __shfl_xor_sync(0xffffffffu, l0, o);
        l1 += __shfl_xor_sync(0xffffffffu, l1, o);
    }
    if (lane == 0) {
        out[(size_t)w * 2] = l0 + bc[0];
        out[(size_t)w * 2 + 1] = l1 + bc[1];
    }
}

// ---------------- launch -----------------------------------------------------

extern "C" void kernel_launch(void* const* d_in, const int* in_sizes, int n_in,
                              void* d_out, int out_size) {
    const float* feat   = (const float*)d_in[0];
    const int* src_ppi  = (const int*)d_in[1];
    const int* dst_ppi  = (const int*)d_in[2];
    const int* src_sim  = (const int*)d_in[3];
    const int* dst_sim  = (const int*)d_in[4];
    const int* pair_src = (const int*)d_in[5];
    const int* pair_dst = (const int*)d_in[6];
    const float* W0_ppi = (const float*)d_in[7];
    const float* b0_ppi = (const float*)d_in[8];
    const float* W0_sim = (const float*)d_in[9];
    const float* b0_sim = (const float*)d_in[10];
    const float* W1_ppi = (const float*)d_in[11];
    const float* b1_ppi = (const float*)d_in[12];
    const float* W1_sim = (const float*)d_in[13];
    const float* b1_sim = (const float*)d_in[14];
    const float* Wc     = (const float*)d_in[15];
    const float* bc     = (const float*)d_in[16];

    const int n = in_sizes[0] / HDIM;
    const int e = in_sizes[1];
    const int p = in_sizes[5];

    float* zout   = (float*)d_out;
    float* logits = (float*)d_out + (size_t)n * HDIM;

    float *hp_ppi, *hp_sim, *hbuf;
    int *ints, *offs, *partial;
    int2 *edges_p, *edges_s;
    cudaGetSymbolAddress((void**)&hp_ppi,  g_hp_ppi);
    cudaGetSymbolAddress((void**)&hp_sim,  g_hp_sim);
    cudaGetSymbolAddress((void**)&hbuf,    g_h);
    cudaGetSymbolAddress((void**)&ints,    g_ints);
    cudaGetSymbolAddress((void**)&offs,    g_offs);
    cudaGetSymbolAddress((void**)&partial, g_partial);
    cudaGetSymbolAddress((void**)&edges_p, g_edges_p);
    cudaGetSymbolAddress((void**)&edges_s, g_edges_s);

    int* deg_out_p = ints;
    int* deg_in_p  = ints + n;
    int* deg_out_s = ints + 2 * n;
    int* deg_in_s  = ints + 3 * n;
    int* cursor_p  = ints + 4 * n;
    int* cursor_s  = ints + 5 * n;
    int* offs_p = offs;
    int* offs_s = offs + NNODES;

    const int TB = 256;
    const int e_blocks    = (e + TB - 1) / TB;
    const int zero_blocks = (6 * n / 4 + TB - 1) / TB;
    const int agg_blocks  = (int)(((long long)n * 32 + TB - 1) / TB);
    const int pair_blocks = (int)(((long long)p * 32 + TB - 1) / TB);
    dim3 gemm_grid((n + 7) / 8, 2);
    dim3 scan_grid(NBLK, 2);

    // ---- CSR build (shared by both layers) ----
    zero_i4_kernel<<<zero_blocks, TB>>>((int4*)ints, 6 * n / 4);
    deg_kernel<<<e_blocks, TB>>>(src_ppi, dst_ppi, deg_out_p, deg_in_p, e);
    deg_kernel<<<e_blocks, TB>>>(src_sim, dst_sim, deg_out_s, deg_in_s, e);
    partial_kernel<<<scan_grid, SCAN_CHUNK>>>(deg_in_p, deg_in_s, partial, n);
    scan_partial_kernel<<<1, 512>>>(partial);
    scan_chunks_kernel<<<scan_grid, SCAN_CHUNK>>>(deg_in_p, deg_in_s, partial, offs, n);
    sort_kernel<<<e_blocks, TB>>>(src_ppi, dst_ppi, deg_out_p, deg_in_p, offs_p, cursor_p, edges_p, e);
    sort_kernel<<<e_blocks, TB>>>(src_sim, dst_sim, deg_out_s, deg_in_s, offs_s, cursor_s, edges_s, e);

    // ---- layer 0 ----
    gemm128_kernel<<<gemm_grid, TB>>>(feat, W0_ppi, hp_ppi, n);
    gemm128_kernel<<<gemm_grid, TB>>>(feat, W0_sim, hp_sim, n);
    aggregate_kernel<<<agg_blocks, TB>>>(hp_ppi, hp_sim, edges_p, offs_p, deg_in_p,
                                         edges_s, offs_s, deg_in_s, b0_ppi, b0_sim, hbuf, n);

    // ---- layer 1 ----
    gemm128_kernel<<<gemm_grid, TB>>>(hbuf, W1_ppi, hp_ppi, n);
    gemm128_kernel<<<gemm_grid, TB>>>(hbuf, W1_sim, hp_sim, n);
    aggregate_kernel<<<agg_blocks, TB>>>(hp_ppi, hp_sim, edges_p, offs_p, deg_in_p,
                                         edges_s, offs_s, deg_in_s, b1_ppi, b1_sim, zout, n);

    // ---- pair classifier ----
    pair_kernel<<<pair_blocks, TB>>>(zout, pair_src, pair_dst, Wc, bc, logits, p);
}

// round 5
// speedup vs baseline: 3.0675x; 2.5398x over previous
#include <cuda_runtime.h>
#include <cuda_fp16.h>
#include <cstddef>

#define NNODES 100000
#define EDGES  1600000
#define HDIM   128
#define SCAN_CHUNK 512
#define NBLK  ((NNODES + SCAN_CHUNK - 1) / SCAN_CHUNK)   // 196

// ---------------- scratch (device globals) -----------------------------------
__device__ __align__(256) __half g_hp_ppi[(size_t)NNODES * HDIM];
__device__ __align__(256) __half g_hp_sim[(size_t)NNODES * HDIM];
__device__ __align__(256) float  g_h     [(size_t)NNODES * HDIM];
__device__ __align__(256) int2   g_edges_p[EDGES];   // {src, coef bits} sorted by dst
__device__ __align__(256) int2   g_edges_s[EDGES];
// [deg_out_p | deg_in_p | deg_out_s | deg_in_s | cursor_p | cursor_s]
__device__ __align__(256) int    g_ints[6 * NNODES];
__device__ __align__(256) int    g_offs[2 * NNODES];
__device__ __align__(256) int    g_partial[2 * 256];

// ---------------- CSR build kernels ------------------------------------------

__global__ void zero_i4_kernel(int4* __restrict__ p, int n4) {
    int i = blockIdx.x * blockDim.x + threadIdx.x;
    if (i < n4) p[i] = make_int4(0, 0, 0, 0);
}

__global__ void deg_kernel(const int* __restrict__ src, const int* __restrict__ dst,
                           int* __restrict__ deg_out, int* __restrict__ deg_in, int e) {
    int i = blockIdx.x * blockDim.x + threadIdx.x;
    if (i < e) {
        atomicAdd(&deg_out[src[i]], 1);
        atomicAdd(&deg_in[dst[i]], 1);
    }
}

__global__ void partial_kernel(const int* __restrict__ din0, const int* __restrict__ din1,
                               int* __restrict__ partial, int n) {
    const int* din = blockIdx.y ? din1 : din0;
    int i = blockIdx.x * SCAN_CHUNK + threadIdx.x;
    int v = (i < n) ? din[i] : 0;
#pragma unroll
    for (int o = 16; o; o >>= 1) v += __shfl_xor_sync(0xffffffffu, v, o);
    __shared__ int ws[16];
    int lane = threadIdx.x & 31, wid = threadIdx.x >> 5;
    if (lane == 0) ws[wid] = v;
    __syncthreads();
    if (threadIdx.x == 0) {
        int s = 0;
        for (int k = 0; k < SCAN_CHUNK / 32; k++) s += ws[k];
        partial[blockIdx.y * 256 + blockIdx.x] = s;
    }
}

__global__ void scan_partial_kernel(int* __restrict__ partial) {
    __shared__ int buf[2][256];
    int r = threadIdx.x >> 8, idx = threadIdx.x & 255;
    buf[r][idx] = (idx < NBLK) ? partial[r * 256 + idx] : 0;
    __syncthreads();
    for (int o = 1; o < 256; o <<= 1) {
        int v = (idx >= o) ? buf[r][idx - o] : 0;
        __syncthreads();
        buf[r][idx] += v;
        __syncthreads();
    }
    partial[r * 256 + idx] = idx ? buf[r][idx - 1] : 0;
}

__global__ void scan_chunks_kernel(const int* __restrict__ din0, const int* __restrict__ din1,
                                   const int* __restrict__ partial, int* __restrict__ offs, int n) {
    const int* din = blockIdx.y ? din1 : din0;
    int i = blockIdx.x * SCAN_CHUNK + threadIdx.x;
    int val = (i < n) ? din[i] : 0;
    int lane = threadIdx.x & 31, wid = threadIdx.x >> 5;
    int incl = val;
#pragma unroll
    for (int o = 1; o < 32; o <<= 1) {
        int t = __shfl_up_sync(0xffffffffu, incl, o);
        if (lane >= o) incl += t;
    }
    __shared__ int ws[16];
    if (lane == 31) ws[wid] = incl;
    __syncthreads();
    if (wid == 0 && lane < 16) {
        int v = ws[lane];
#pragma unroll
        for (int o = 1; o < 16; o <<= 1) {
            int t = __shfl_up_sync(0x0000ffffu, v, o);
            if (lane >= o) v += t;
        }
        ws[lane] = v;
    }
    __syncthreads();
    int base = (wid ? ws[wid - 1] : 0) + partial[blockIdx.y * 256 + blockIdx.x];
    if (i < n) offs[blockIdx.y * NNODES + i] = base + incl - val;
}

__global__ void sort_kernel(const int* __restrict__ src, const int* __restrict__ dst,
                            const int* __restrict__ deg_out, const int* __restrict__ deg_in,
                            const int* __restrict__ offs, int* __restrict__ cursor,
                            int2* __restrict__ edges, int e) {
    int i = blockIdx.x * blockDim.x + threadIdx.x;
    if (i >= e) return;
    int s = src[i], d = dst[i];
    float c = rsqrtf(fmaxf((float)deg_out[s], 1.0f)) * rsqrtf(fmaxf((float)deg_in[d], 1.0f));
    int slot = offs[d] + atomicAdd(&cursor[d], 1);
    edges[slot] = make_int2(s, __float_as_int(c));
}

// ---------------- register-tiled GEMM, fp16 output ---------------------------
// Y[r, c] = sum_k X[r,k] W[k,c]; block tile 128x128, 256 threads, 8x8 per thread
#define GT_M 128
#define GT_K 16

__global__ __launch_bounds__(256) void gemm_h_kernel(const float* __restrict__ X,
                                                     const float* __restrict__ W,
                                                     __half* __restrict__ Y, int nrows) {
    __shared__ float Xs[GT_K][GT_M + 4];
    __shared__ float Ws[GT_K][HDIM + 4];
    const int tid = threadIdx.x;
    const int tx = tid & 15, ty = tid >> 4;
    const int row0 = blockIdx.x * GT_M;

    float acc[8][8];
#pragma unroll
    for (int i = 0; i < 8; i++)
#pragma unroll
        for (int j = 0; j < 8; j++) acc[i][j] = 0.f;

    for (int k0 = 0; k0 < HDIM; k0 += GT_K) {
        // stage X tile: Xs[kk][m] = X[(row0+m)*H + k0+kk]
        {
            int t = tid;
            for (int rep = 0; rep < 2; rep++, t += 256) {
                int m = t >> 2, kk4 = (t & 3) * 4;
                int r = row0 + m;
                float4 v = (r < nrows) ? *(const float4*)(X + (size_t)r * HDIM + k0 + kk4)
                                       : make_float4(0.f, 0.f, 0.f, 0.f);
                Xs[kk4][m] = v.x; Xs[kk4 + 1][m] = v.y;
                Xs[kk4 + 2][m] = v.z; Xs[kk4 + 3][m] = v.w;
            }
        }
        // stage W slab: Ws[kk][c] = W[(k0+kk)*H + c]
        {
            int t = tid;
            for (int rep = 0; rep < 2; rep++, t += 256) {
                int kk = t >> 5, c4 = (t & 31) * 4;
                *(float4*)&Ws[kk][c4] = *(const float4*)(W + (size_t)(k0 + kk) * HDIM + c4);
            }
        }
        __syncthreads();
#pragma unroll
        for (int kk = 0; kk < GT_K; kk++) {
            float a[8], b[8];
#pragma unroll
            for (int i = 0; i < 8; i++) a[i] = Xs[kk][ty * 8 + i];
#pragma unroll
            for (int j = 0; j < 8; j++) b[j] = Ws[kk][tx * 8 + j];
#pragma unroll
            for (int i = 0; i < 8; i++)
#pragma unroll
                for (int j = 0; j < 8; j++) acc[i][j] += a[i] * b[j];
        }
        __syncthreads();
    }
#pragma unroll
    for (int i = 0; i < 8; i++) {
        int r = row0 + ty * 8 + i;
        if (r < nrows) {
            __half2 h[4];
#pragma unroll
            for (int j = 0; j < 4; j++) h[j] = __floats2half2_rn(acc[i][2 * j], acc[i][2 * j + 1]);
            *(uint4*)(Y + (size_t)r * HDIM + tx * 8) = *(uint4*)h;
        }
    }
}

// ---------------- fused aggregate (fp16 gathers, fp32 accum) ------------------
__global__ void aggregate_kernel(const __half* __restrict__ hp_p, const __half* __restrict__ hp_s,
                                 const int2* __restrict__ ep, const int* __restrict__ offs_p,
                                 const int* __restrict__ deg_p,
                                 const int2* __restrict__ es, const int* __restrict__ offs_s,
                                 const int* __restrict__ deg_s,
                                 const float* __restrict__ bp, const float* __restrict__ bs,
                                 float* __restrict__ out, int n) {
    int w = (blockIdx.x * blockDim.x + threadIdx.x) >> 5;
    int lane = threadIdx.x & 31;
    if (w >= n) return;
    float4 v = make_float4(0.f, 0.f, 0.f, 0.f);

#pragma unroll 1
    for (int rel = 0; rel < 2; rel++) {
        const int2* ed = rel ? es : ep;
        const __half* hp = rel ? hp_s : hp_p;
        int st = rel ? offs_s[w] : offs_p[w];
        int en = st + (rel ? deg_s[w] : deg_p[w]);
        int j = st;
        for (; j + 1 < en; j += 2) {
            int2 e0 = __ldg(&ed[j]);
            int2 e1 = __ldg(&ed[j + 1]);
            uint2 r0 = __ldg((const uint2*)(hp + (size_t)e0.x * HDIM) + lane);
            uint2 r1 = __ldg((const uint2*)(hp + (size_t)e1.x * HDIM) + lane);
            float c0 = __int_as_float(e0.y), c1 = __int_as_float(e1.y);
            float2 a0 = __half22float2(*(__half2*)&r0.x);
            float2 a1 = __half22float2(*(__half2*)&r0.y);
            float2 b0 = __half22float2(*(__half2*)&r1.x);
            float2 b1 = __half22float2(*(__half2*)&r1.y);
            v.x += c0 * a0.x + c1 * b0.x;
            v.y += c0 * a0.y + c1 * b0.y;
            v.z += c0 * a1.x + c1 * b1.x;
            v.w += c0 * a1.y + c1 * b1.y;
        }
        if (j < en) {
            int2 e0 = __ldg(&ed[j]);
            uint2 r0 = __ldg((const uint2*)(hp + (size_t)e0.x * HDIM) + lane);
            float c0 = __int_as_float(e0.y);
            float2 a0 = __half22float2(*(__half2*)&r0.x);
            float2 a1 = __half22float2(*(__half2*)&r0.y);
            v.x += c0 * a0.x; v.y += c0 * a0.y; v.z += c0 * a1.x; v.w += c0 * a1.y;
        }
    }
    float4 b1 = ((const float4*)bp)[lane];
    float4 b2 = ((const float4*)bs)[lane];
    float4 r;
    r.x = fmaxf(0.5f * (v.x + b1.x + b2.x), 0.f);
    r.y = fmaxf(0.5f * (v.y + b1.y + b2.y), 0.f);
    r.z = fmaxf(0.5f * (v.z + b1.z + b2.z), 0.f);
    r.w = fmaxf(0.5f * (v.w + b1.w + b2.w), 0.f);
    *((float4*)(out + (size_t)w * HDIM) + lane) = r;
}

// ---------------- pair classifier --------------------------------------------
__global__ void pair_kernel(const float* __restrict__ z,
                            const int* __restrict__ ps, const int* __restrict__ pd,
                            const float* __restrict__ Wc, const float* __restrict__ bc,
                            float* __restrict__ out, int p) {
    int w = (blockIdx.x * blockDim.x + threadIdx.x) >> 5;
    int lane = threadIdx.x & 31;
    if (w >= p) return;
    int s = __ldg(&ps[w]), d = __ldg(&pd[w]);
    float4 zs = __ldg((const float4*)(z + (size_t)s * HDIM) + lane);
    float4 zd = __ldg((const float4*)(z + (size_t)d * HDIM) + lane);
    const float4* wc4 = (const float4*)Wc;
    float4 wa = wc4[lane * 2], wb = wc4[lane * 2 + 1];
    float l0 = zs.x * wa.x + zs.y * wa.z + zs.z * wb.x + zs.w * wb.z;
    float l1 = zs.x * wa.y + zs.y * wa.w + zs.z * wb.y + zs.w * wb.w;
    float4 wcv = wc4[64 + lane * 2], wd = wc4[64 + lane * 2 + 1];
    l0 += zd.x * wcv.x + zd.y * wcv.z + zd.z * wd.x + zd.w * wd.z;
    l1 += zd.x * wcv.y + zd.y * wcv.w + zd.z * wd.y + zd.w * wd.w;
#pragma unroll
    for (int o = 16; o; o >>= 1) {
        l0 += __shfl_xor_sync(0xffffffffu, l0, o);
        l1 += __shfl_xor_sync(0xffffffffu, l1, o);
    }
    if (lane == 0) {
        out[(size_t)w * 2] = l0 + bc[0];
        out[(size_t)w * 2 + 1] = l1 + bc[1];
    }
}

// ---------------- launch -----------------------------------------------------

extern "C" void kernel_launch(void* const* d_in, const int* in_sizes, int n_in,
                              void* d_out, int out_size) {
    const float* feat   = (const float*)d_in[0];
    const int* src_ppi  = (const int*)d_in[1];
    const int* dst_ppi  = (const int*)d_in[2];
    const int* src_sim  = (const int*)d_in[3];
    const int* dst_sim  = (const int*)d_in[4];
    const int* pair_src = (const int*)d_in[5];
    const int* pair_dst = (const int*)d_in[6];
    const float* W0_ppi = (const float*)d_in[7];
    const float* b0_ppi = (const float*)d_in[8];
    const float* W0_sim = (const float*)d_in[9];
    const float* b0_sim = (const float*)d_in[10];
    const float* W1_ppi = (const float*)d_in[11];
    const float* b1_ppi = (const float*)d_in[12];
    const float* W1_sim = (const float*)d_in[13];
    const float* b1_sim = (const float*)d_in[14];
    const float* Wc     = (const float*)d_in[15];
    const float* bc     = (const float*)d_in[16];

    const int n = in_sizes[0] / HDIM;
    const int e = in_sizes[1];
    const int p = in_sizes[5];

    float* zout   = (float*)d_out;
    float* logits = (float*)d_out + (size_t)n * HDIM;

    __half *hp_ppi, *hp_sim;
    float *hbuf;
    int *ints, *offs, *partial;
    int2 *edges_p, *edges_s;
    cudaGetSymbolAddress((void**)&hp_ppi,  g_hp_ppi);
    cudaGetSymbolAddress((void**)&hp_sim,  g_hp_sim);
    cudaGetSymbolAddress((void**)&hbuf,    g_h);
    cudaGetSymbolAddress((void**)&ints,    g_ints);
    cudaGetSymbolAddress((void**)&offs,    g_offs);
    cudaGetSymbolAddress((void**)&partial, g_partial);
    cudaGetSymbolAddress((void**)&edges_p, g_edges_p);
    cudaGetSymbolAddress((void**)&edges_s, g_edges_s);

    int* deg_out_p = ints;
    int* deg_in_p  = ints + n;
    int* deg_out_s = ints + 2 * n;
    int* deg_in_s  = ints + 3 * n;
    int* cursor_p  = ints + 4 * n;
    int* cursor_s  = ints + 5 * n;
    int* offs_p = offs;
    int* offs_s = offs + NNODES;

    const int TB = 256;
    const int e_blocks    = (e + TB - 1) / TB;
    const int zero_blocks = (6 * n / 4 + TB - 1) / TB;
    const int agg_blocks  = (int)(((long long)n * 32 + TB - 1) / TB);
    const int pair_blocks = (int)(((long long)p * 32 + TB - 1) / TB);
    const int gemm_blocks = (n + GT_M - 1) / GT_M;
    dim3 scan_grid(NBLK, 2);

    // ---- CSR build (shared by both layers) ----
    zero_i4_kernel<<<zero_blocks, TB>>>((int4*)ints, 6 * n / 4);
    deg_kernel<<<e_blocks, TB>>>(src_ppi, dst_ppi, deg_out_p, deg_in_p, e);
    deg_kernel<<<e_blocks, TB>>>(src_sim, dst_sim, deg_out_s, deg_in_s, e);
    partial_kernel<<<scan_grid, SCAN_CHUNK>>>(deg_in_p, deg_in_s, partial, n);
    scan_partial_kernel<<<1, 512>>>(partial);
    scan_chunks_kernel<<<scan_grid, SCAN_CHUNK>>>(deg_in_p, deg_in_s, partial, offs, n);
    sort_kernel<<<e_blocks, TB>>>(src_ppi, dst_ppi, deg_out_p, deg_in_p, offs_p, cursor_p, edges_p, e);
    sort_kernel<<<e_blocks, TB>>>(src_sim, dst_sim, deg_out_s, deg_in_s, offs_s, cursor_s, edges_s, e);

    // ---- layer 0 ----
    gemm_h_kernel<<<gemm_blocks, 256>>>(feat, W0_ppi, hp_ppi, n);
    gemm_h_kernel<<<gemm_blocks, 256>>>(feat, W0_sim, hp_sim, n);
    aggregate_kernel<<<agg_blocks, TB>>>(hp_ppi, hp_sim, edges_p, offs_p, deg_in_p,
                                         edges_s, offs_s, deg_in_s, b0_ppi, b0_sim, hbuf, n);

    // ---- layer 1 ----
    gemm_h_kernel<<<gemm_blocks, 256>>>(hbuf, W1_ppi, hp_ppi, n);
    gemm_h_kernel<<<gemm_blocks, 256>>>(hbuf, W1_sim, hp_sim, n);
    aggregate_kernel<<<agg_blocks, TB>>>(hp_ppi, hp_sim, edges_p, offs_p, deg_in_p,
                                         edges_s, offs_s, deg_in_s, b1_ppi, b1_sim, zout, n);

    // ---- pair classifier ----
    pair_kernel<<<pair_blocks, TB>>>(zout, pair_src, pair_dst, Wc, bc, logits, p);
}

// round 6
// speedup vs baseline: 4.4170x; 1.4400x over previous
#include <cuda_runtime.h>
#include <cuda_fp16.h>
#include <cstddef>
#include <cstdint>

#define NNODES 100000
#define EDGES  1600000
#define HDIM   128
#define SCAN_CHUNK 512
#define NBLK  ((NNODES + SCAN_CHUNK - 1) / SCAN_CHUNK)   // 196

// ---------------- scratch (device globals) -----------------------------------
__device__ __align__(256) __half g_xh    [(size_t)NNODES * HDIM];   // feat fp16
__device__ __align__(256) __half g_h16   [(size_t)NNODES * HDIM];   // layer0 out fp16
__device__ __align__(256) __half g_hp_ppi[(size_t)NNODES * HDIM];
__device__ __align__(256) __half g_hp_sim[(size_t)NNODES * HDIM];
__device__ __align__(256) __half g_wh[4 * HDIM * HDIM];             // 4 weights fp16
__device__ __align__(256) int2   g_edges_p[EDGES];
__device__ __align__(256) int2   g_edges_s[EDGES];
__device__ __align__(256) int    g_ints[6 * NNODES];
__device__ __align__(256) int    g_offs[2 * NNODES];
__device__ __align__(256) int    g_partial[2 * 256];

// ---------------- CSR build kernels ------------------------------------------

__global__ void zero_i4_kernel(int4* __restrict__ p, int n4) {
    int i = blockIdx.x * blockDim.x + threadIdx.x;
    if (i < n4) p[i] = make_int4(0, 0, 0, 0);
}

__global__ void deg_kernel(const int* __restrict__ src, const int* __restrict__ dst,
                           int* __restrict__ deg_out, int* __restrict__ deg_in, int e) {
    int i = blockIdx.x * blockDim.x + threadIdx.x;
    if (i < e) {
        atomicAdd(&deg_out[src[i]], 1);
        atomicAdd(&deg_in[dst[i]], 1);
    }
}

__global__ void partial_kernel(const int* __restrict__ din0, const int* __restrict__ din1,
                               int* __restrict__ partial, int n) {
    const int* din = blockIdx.y ? din1 : din0;
    int i = blockIdx.x * SCAN_CHUNK + threadIdx.x;
    int v = (i < n) ? din[i] : 0;
#pragma unroll
    for (int o = 16; o; o >>= 1) v += __shfl_xor_sync(0xffffffffu, v, o);
    __shared__ int ws[16];
    int lane = threadIdx.x & 31, wid = threadIdx.x >> 5;
    if (lane == 0) ws[wid] = v;
    __syncthreads();
    if (threadIdx.x == 0) {
        int s = 0;
        for (int k = 0; k < SCAN_CHUNK / 32; k++) s += ws[k];
        partial[blockIdx.y * 256 + blockIdx.x] = s;
    }
}

__global__ void scan_partial_kernel(int* __restrict__ partial) {
    __shared__ int buf[2][256];
    int r = threadIdx.x >> 8, idx = threadIdx.x & 255;
    buf[r][idx] = (idx < NBLK) ? partial[r * 256 + idx] : 0;
    __syncthreads();
    for (int o = 1; o < 256; o <<= 1) {
        int v = (idx >= o) ? buf[r][idx - o] : 0;
        __syncthreads();
        buf[r][idx] += v;
        __syncthreads();
    }
    partial[r * 256 + idx] = idx ? buf[r][idx - 1] : 0;
}

__global__ void scan_chunks_kernel(const int* __restrict__ din0, const int* __restrict__ din1,
                                   const int* __restrict__ partial, int* __restrict__ offs, int n) {
    const int* din = blockIdx.y ? din1 : din0;
    int i = blockIdx.x * SCAN_CHUNK + threadIdx.x;
    int val = (i < n) ? din[i] : 0;
    int lane = threadIdx.x & 31, wid = threadIdx.x >> 5;
    int incl = val;
#pragma unroll
    for (int o = 1; o < 32; o <<= 1) {
        int t = __shfl_up_sync(0xffffffffu, incl, o);
        if (lane >= o) incl += t;
    }
    __shared__ int ws[16];
    if (lane == 31) ws[wid] = incl;
    __syncthreads();
    if (wid == 0 && lane < 16) {
        int v = ws[lane];
#pragma unroll
        for (int o = 1; o < 16; o <<= 1) {
            int t = __shfl_up_sync(0x0000ffffu, v, o);
            if (lane >= o) v += t;
        }
        ws[lane] = v;
    }
    __syncthreads();
    int base = (wid ? ws[wid - 1] : 0) + partial[blockIdx.y * 256 + blockIdx.x];
    if (i < n) offs[blockIdx.y * NNODES + i] = base + incl - val;
}

__global__ void sort_kernel(const int* __restrict__ src, const int* __restrict__ dst,
                            const int* __restrict__ deg_out, const int* __restrict__ deg_in,
                            const int* __restrict__ offs, int* __restrict__ cursor,
                            int2* __restrict__ edges, int e) {
    int i = blockIdx.x * blockDim.x + threadIdx.x;
    if (i >= e) return;
    int s = src[i], d = dst[i];
    float c = rsqrtf(fmaxf((float)deg_out[s], 1.0f)) * rsqrtf(fmaxf((float)deg_in[d], 1.0f));
    int slot = offs[d] + atomicAdd(&cursor[d], 1);
    edges[slot] = make_int2(s, __float_as_int(c));
}

// ---------------- fp32 -> fp16 converters ------------------------------------

__global__ void convert_x_kernel(const float* __restrict__ x, __half* __restrict__ y, int n4) {
    int i = blockIdx.x * blockDim.x + threadIdx.x;
    if (i < n4) {
        float4 v = ((const float4*)x)[i];
        __half2 h[2];
        h[0] = __floats2half2_rn(v.x, v.y);
        h[1] = __floats2half2_rn(v.z, v.w);
        ((uint2*)y)[i] = *(uint2*)h;
    }
}

__global__ void convert_w_kernel(const float* __restrict__ w0p, const float* __restrict__ w0s,
                                 const float* __restrict__ w1p, const float* __restrict__ w1s,
                                 __half* __restrict__ out) {
    int i = blockIdx.x * blockDim.x + threadIdx.x;
    if (i < HDIM * HDIM) {
        out[i]                     = __float2half(w0p[i]);
        out[HDIM * HDIM + i]       = __float2half(w0s[i]);
        out[2 * HDIM * HDIM + i]   = __float2half(w1p[i]);
        out[3 * HDIM * HDIM + i]   = __float2half(w1s[i]);
    }
}

// ---------------- HMMA GEMM: Y[M,128] = X[M,128] @ W[128,128], all fp16 ------
// 256 threads = 8 warps; block tile 128 rows; warp owns 16 rows x 128 cols.
__global__ __launch_bounds__(256) void gemm_mma_kernel(const __half* __restrict__ X,
                                                       const __half* __restrict__ W,
                                                       __half* __restrict__ Y, int nrows) {
    __shared__ __half Xs[128][40];    // K-chunk 32, pad 8 -> row stride 80B (20 banks)
    __shared__ __half Ws[32][136];    // pad 8 -> row stride 272B (4 banks)
    const int tid  = threadIdx.x;
    const int warp = tid >> 5, lane = tid & 31;
    const int row0 = blockIdx.x * 128;
    const int wrow = warp * 16;

    float acc[16][4];
#pragma unroll
    for (int t = 0; t < 16; t++)
#pragma unroll
        for (int j = 0; j < 4; j++) acc[t][j] = 0.f;

    for (int k0 = 0; k0 < HDIM; k0 += 32) {
        // stage Xs: 128 rows x 32 halves (4 uint4 per row)
#pragma unroll
        for (int t = tid; t < 512; t += 256) {
            int r = t >> 2, c8 = (t & 3) * 8;
            int gr = row0 + r;
            uint4 v = make_uint4(0u, 0u, 0u, 0u);
            if (gr < nrows) v = *(const uint4*)(X + (size_t)gr * HDIM + k0 + c8);
            *(uint4*)&Xs[r][c8] = v;
        }
        // stage Ws: 32 rows x 128 halves (16 uint4 per row)
#pragma unroll
        for (int t = tid; t < 512; t += 256) {
            int r = t >> 4, c8 = (t & 15) * 8;
            *(uint4*)&Ws[r][c8] = *(const uint4*)(W + (size_t)(k0 + r) * HDIM + c8);
        }
        __syncthreads();

#pragma unroll
        for (int ks = 0; ks < 2; ks++) {
            const int kk = ks * 16;
            uint32_t a[4];
            {
                const __half* pa = &Xs[wrow + (lane & 7) + 8 * ((lane >> 3) & 1)][kk + 8 * (lane >> 4)];
                uint32_t addr = (uint32_t)__cvta_generic_to_shared(pa);
                asm volatile("ldmatrix.sync.aligned.m8n8.x4.shared.b16 {%0,%1,%2,%3}, [%4];"
                             : "=r"(a[0]), "=r"(a[1]), "=r"(a[2]), "=r"(a[3]) : "r"(addr));
            }
#pragma unroll
            for (int nt = 0; nt < 8; nt++) {
                const int n0 = nt * 16;
                uint32_t b[4];
                const __half* pb = &Ws[kk + (lane & 7) + 8 * ((lane >> 3) & 1)][n0 + 8 * (lane >> 4)];
                uint32_t addr = (uint32_t)__cvta_generic_to_shared(pb);
                asm volatile("ldmatrix.sync.aligned.m8n8.x4.trans.shared.b16 {%0,%1,%2,%3}, [%4];"
                             : "=r"(b[0]), "=r"(b[1]), "=r"(b[2]), "=r"(b[3]) : "r"(addr));
                asm volatile("mma.sync.aligned.m16n8k16.row.col.f32.f16.f16.f32 "
                             "{%0,%1,%2,%3}, {%4,%5,%6,%7}, {%8,%9}, {%0,%1,%2,%3};"
                             : "+f"(acc[2 * nt][0]), "+f"(acc[2 * nt][1]),
                               "+f"(acc[2 * nt][2]), "+f"(acc[2 * nt][3])
                             : "r"(a[0]), "r"(a[1]), "r"(a[2]), "r"(a[3]), "r"(b[0]), "r"(b[1]));
                asm volatile("mma.sync.aligned.m16n8k16.row.col.f32.f16.f16.f32 "
                             "{%0,%1,%2,%3}, {%4,%5,%6,%7}, {%8,%9}, {%0,%1,%2,%3};"
                             : "+f"(acc[2 * nt + 1][0]), "+f"(acc[2 * nt + 1][1]),
                               "+f"(acc[2 * nt + 1][2]), "+f"(acc[2 * nt + 1][3])
                             : "r"(a[0]), "r"(a[1]), "r"(a[2]), "r"(a[3]), "r"(b[2]), "r"(b[3]));
            }
        }
        __syncthreads();
    }

    // epilogue: lane layout of m16n8 acc -> rows (lane>>2) and (lane>>2)+8
    const int rlo = row0 + wrow + (lane >> 2);
    const int rhi = rlo + 8;
    const int cbase = (lane & 3) * 2;
#pragma unroll
    for (int nt = 0; nt < 16; nt++) {
        int c = nt * 8 + cbase;
        if (rlo < nrows)
            *(__half2*)(Y + (size_t)rlo * HDIM + c) = __floats2half2_rn(acc[nt][0], acc[nt][1]);
        if (rhi < nrows)
            *(__half2*)(Y + (size_t)rhi * HDIM + c) = __floats2half2_rn(acc[nt][2], acc[nt][3]);
    }
}

// ---------------- fused aggregate (fp16 gathers, fp32 accum) ------------------
template <typename OutT>
__global__ void aggregate_kernel(const __half* __restrict__ hp_p, const __half* __restrict__ hp_s,
                                 const int2* __restrict__ ep, const int* __restrict__ offs_p,
                                 const int* __restrict__ deg_p,
                                 const int2* __restrict__ es, const int* __restrict__ offs_s,
                                 const int* __restrict__ deg_s,
                                 const float* __restrict__ bp, const float* __restrict__ bs,
                                 OutT* __restrict__ out, int n) {
    int w = (blockIdx.x * blockDim.x + threadIdx.x) >> 5;
    int lane = threadIdx.x & 31;
    if (w >= n) return;
    float4 v = make_float4(0.f, 0.f, 0.f, 0.f);

#pragma unroll 1
    for (int rel = 0; rel < 2; rel++) {
        const int2* ed = rel ? es : ep;
        const __half* hp = rel ? hp_s : hp_p;
        int st = rel ? offs_s[w] : offs_p[w];
        int en = st + (rel ? deg_s[w] : deg_p[w]);
        int j = st;
        for (; j + 1 < en; j += 2) {
            int2 e0 = __ldg(&ed[j]);
            int2 e1 = __ldg(&ed[j + 1]);
            uint2 r0 = __ldg((const uint2*)(hp + (size_t)e0.x * HDIM) + lane);
            uint2 r1 = __ldg((const uint2*)(hp + (size_t)e1.x * HDIM) + lane);
            float c0 = __int_as_float(e0.y), c1 = __int_as_float(e1.y);
            float2 a0 = __half22float2(*(__half2*)&r0.x);
            float2 a1 = __half22float2(*(__half2*)&r0.y);
            float2 b0 = __half22float2(*(__half2*)&r1.x);
            float2 b1 = __half22float2(*(__half2*)&r1.y);
            v.x += c0 * a0.x + c1 * b0.x;
            v.y += c0 * a0.y + c1 * b0.y;
            v.z += c0 * a1.x + c1 * b1.x;
            v.w += c0 * a1.y + c1 * b1.y;
        }
        if (j < en) {
            int2 e0 = __ldg(&ed[j]);
            uint2 r0 = __ldg((const uint2*)(hp + (size_t)e0.x * HDIM) + lane);
            float c0 = __int_as_float(e0.y);
            float2 a0 = __half22float2(*(__half2*)&r0.x);
            float2 a1 = __half22float2(*(__half2*)&r0.y);
            v.x += c0 * a0.x; v.y += c0 * a0.y; v.z += c0 * a1.x; v.w += c0 * a1.y;
        }
    }
    float4 b1 = ((const float4*)bp)[lane];
    float4 b2 = ((const float4*)bs)[lane];
    float4 r;
    r.x = fmaxf(0.5f * (v.x + b1.x + b2.x), 0.f);
    r.y = fmaxf(0.5f * (v.y + b1.y + b2.y), 0.f);
    r.z = fmaxf(0.5f * (v.z + b1.z + b2.z), 0.f);
    r.w = fmaxf(0.5f * (v.w + b1.w + b2.w), 0.f);
    if (sizeof(OutT) == 4) {
        *((float4*)((float*)out + (size_t)w * HDIM) + lane) = r;
    } else {
        __half2 h[2];
        h[0] = __floats2half2_rn(r.x, r.y);
        h[1] = __floats2half2_rn(r.z, r.w);
        *((uint2*)((__half*)out + (size_t)w * HDIM) + lane) = *(uint2*)h;
    }
}

// ---------------- pair classifier --------------------------------------------
__global__ void pair_kernel(const float* __restrict__ z,
                            const int* __restrict__ ps, const int* __restrict__ pd,
                            const float* __restrict__ Wc, const float* __restrict__ bc,
                            float* __restrict__ out, int p) {
    int w = (blockIdx.x * blockDim.x + threadIdx.x) >> 5;
    int lane = threadIdx.x & 31;
    if (w >= p) return;
    int s = __ldg(&ps[w]), d = __ldg(&pd[w]);
    float4 zs = __ldg((const float4*)(z + (size_t)s * HDIM) + lane);
    float4 zd = __ldg((const float4*)(z + (size_t)d * HDIM) + lane);
    const float4* wc4 = (const float4*)Wc;
    float4 wa = wc4[lane * 2], wb = wc4[lane * 2 + 1];
    float l0 = zs.x * wa.x + zs.y * wa.z + zs.z * wb.x + zs.w * wb.z;
    float l1 = zs.x * wa.y + zs.y * wa.w + zs.z * wb.y + zs.w * wb.w;
    float4 wcv = wc4[64 + lane * 2], wd = wc4[64 + lane * 2 + 1];
    l0 += zd.x * wcv.x + zd.y * wcv.z + zd.z * wd.x + zd.w * wd.z;
    l1 += zd.x * wcv.y + zd.y * wcv.w + zd.z * wd.y + zd.w * wd.w;
#pragma unroll
    for (int o = 16; o; o >>= 1) {
        l0 += __shfl_xor_sync(0xffffffffu, l0, o);
        l1 += __shfl_xor_sync(0xffffffffu, l1, o);
    }
    if (lane == 0) {
        out[(size_t)w * 2] = l0 + bc[0];
        out[(size_t)w * 2 + 1] = l1 + bc[1];
    }
}

// ---------------- launch -----------------------------------------------------

extern "C" void kernel_launch(void* const* d_in, const int* in_sizes, int n_in,
                              void* d_out, int out_size) {
    const float* feat   = (const float*)d_in[0];
    const int* src_ppi  = (const int*)d_in[1];
    const int* dst_ppi  = (const int*)d_in[2];
    const int* src_sim  = (const int*)d_in[3];
    const int* dst_sim  = (const int*)d_in[4];
    const int* pair_src = (const int*)d_in[5];
    const int* pair_dst = (const int*)d_in[6];
    const float* W0_ppi = (const float*)d_in[7];
    const float* b0_ppi = (const float*)d_in[8];
    const float* W0_sim = (const float*)d_in[9];
    const float* b0_sim = (const float*)d_in[10];
    const float* W1_ppi = (const float*)d_in[11];
    const float* b1_ppi = (const float*)d_in[12];
    const float* W1_sim = (const float*)d_in[13];
    const float* b1_sim = (const float*)d_in[14];
    const float* Wc     = (const float*)d_in[15];
    const float* bc     = (const float*)d_in[16];

    const int n = in_sizes[0] / HDIM;
    const int e = in_sizes[1];
    const int p = in_sizes[5];

    float* zout   = (float*)d_out;
    float* logits = (float*)d_out + (size_t)n * HDIM;

    __half *xh, *h16, *hp_ppi, *hp_sim, *wh;
    int *ints, *offs, *partial;
    int2 *edges_p, *edges_s;
    cudaGetSymbolAddress((void**)&xh,      g_xh);
    cudaGetSymbolAddress((void**)&h16,     g_h16);
    cudaGetSymbolAddress((void**)&hp_ppi,  g_hp_ppi);
    cudaGetSymbolAddress((void**)&hp_sim,  g_hp_sim);
    cudaGetSymbolAddress((void**)&wh,      g_wh);
    cudaGetSymbolAddress((void**)&ints,    g_ints);
    cudaGetSymbolAddress((void**)&offs,    g_offs);
    cudaGetSymbolAddress((void**)&partial, g_partial);
    cudaGetSymbolAddress((void**)&edges_p, g_edges_p);
    cudaGetSymbolAddress((void**)&edges_s, g_edges_s);

    int* deg_out_p = ints;
    int* deg_in_p  = ints + n;
    int* deg_out_s = ints + 2 * n;
    int* deg_in_s  = ints + 3 * n;
    int* cursor_p  = ints + 4 * n;
    int* cursor_s  = ints + 5 * n;
    int* offs_p = offs;
    int* offs_s = offs + NNODES;

    __half* w0p = wh;
    __half* w0s = wh + HDIM * HDIM;
    __half* w1p = wh + 2 * HDIM * HDIM;
    __half* w1s = wh + 3 * HDIM * HDIM;

    const int TB = 256;
    const int nh = n * HDIM;
    const int e_blocks    = (e + TB - 1) / TB;
    const int zero_blocks = (6 * n / 4 + TB - 1) / TB;
    const int agg_blocks  = (int)(((long long)n * 32 + TB - 1) / TB);
    const int pair_blocks = (int)(((long long)p * 32 + TB - 1) / TB);
    const int gemm_blocks = (n + 127) / 128;
    const int cvx_blocks  = (nh / 4 + TB - 1) / TB;
    const int cvw_blocks  = (HDIM * HDIM + TB - 1) / TB;
    dim3 scan_grid(NBLK, 2);

    // ---- CSR build (shared by both layers) ----
    zero_i4_kernel<<<zero_blocks, TB>>>((int4*)ints, 6 * n / 4);
    deg_kernel<<<e_blocks, TB>>>(src_ppi, dst_ppi, deg_out_p, deg_in_p, e);
    deg_kernel<<<e_blocks, TB>>>(src_sim, dst_sim, deg_out_s, deg_in_s, e);
    partial_kernel<<<scan_grid, SCAN_CHUNK>>>(deg_in_p, deg_in_s, partial, n);
    scan_partial_kernel<<<1, 512>>>(partial);
    scan_chunks_kernel<<<scan_grid, SCAN_CHUNK>>>(deg_in_p, deg_in_s, partial, offs, n);
    sort_kernel<<<e_blocks, TB>>>(src_ppi, dst_ppi, deg_out_p, deg_in_p, offs_p, cursor_p, edges_p, e);
    sort_kernel<<<e_blocks, TB>>>(src_sim, dst_sim, deg_out_s, deg_in_s, offs_s, cursor_s, edges_s, e);

    // ---- fp16 conversions ----
    convert_x_kernel<<<cvx_blocks, TB>>>(feat, xh, nh / 4);
    convert_w_kernel<<<cvw_blocks, TB>>>(W0_ppi, W0_sim, W1_ppi, W1_sim, wh);

    // ---- layer 0 ----
    gemm_mma_kernel<<<gemm_blocks, 256>>>(xh, w0p, hp_ppi, n);
    gemm_mma_kernel<<<gemm_blocks, 256>>>(xh, w0s, hp_sim, n);
    aggregate_kernel<__half><<<agg_blocks, TB>>>(hp_ppi, hp_sim, edges_p, offs_p, deg_in_p,
                                                 edges_s, offs_s, deg_in_s, b0_ppi, b0_sim, h16, n);

    // ---- layer 1 ----
    gemm_mma_kernel<<<gemm_blocks, 256>>>(h16, w1p, hp_ppi, n);
    gemm_mma_kernel<<<gemm_blocks, 256>>>(h16, w1s, hp_sim, n);
    aggregate_kernel<float><<<agg_blocks, TB>>>(hp_ppi, hp_sim, edges_p, offs_p, deg_in_p,
                                                edges_s, offs_s, deg_in_s, b1_ppi, b1_sim, zout, n);

    // ---- pair classifier ----
    pair_kernel<<<pair_blocks, TB>>>(zout, pair_src, pair_dst, Wc, bc, logits, p);
}

// round 7
// speedup vs baseline: 4.4323x; 1.0034x over previous
#include <cuda_runtime.h>
#include <cuda_fp16.h>
#include <cstddef>
#include <cstdint>

#define NNODES 100000
#define EDGES  1600000
#define HDIM   128

// ---------------- scratch (device globals) -----------------------------------
__device__ __align__(256) __half g_xh    [(size_t)NNODES * HDIM];   // feat fp16
__device__ __align__(256) __half g_h16   [(size_t)NNODES * HDIM];   // layer0 out fp16
__device__ __align__(256) __half g_hp_ppi[(size_t)NNODES * HDIM];
__device__ __align__(256) __half g_hp_sim[(size_t)NNODES * HDIM];
__device__ __align__(256) __half g_wh[4 * HDIM * HDIM];             // 4 weights fp16
__device__ __align__(256) int2   g_edges_p[EDGES];
__device__ __align__(256) int2   g_edges_s[EDGES];
__device__ __align__(256) int    g_ints[6 * NNODES];
__device__ __align__(256) int    g_offs[2 * NNODES];

// ---------------- CSR build kernels ------------------------------------------

__global__ void zero_i4_kernel(int4* __restrict__ p, int n4) {
    int i = blockIdx.x * blockDim.x + threadIdx.x;
    if (i < n4) p[i] = make_int4(0, 0, 0, 0);
}

// both relations in one launch: i<e -> ppi, else sim
__global__ void deg2_kernel(const int* __restrict__ src_p, const int* __restrict__ dst_p,
                            const int* __restrict__ src_s, const int* __restrict__ dst_s,
                            int* __restrict__ ints, int n, int e) {
    int i = blockIdx.x * blockDim.x + threadIdx.x;
    if (i < e) {
        atomicAdd(&ints[src_p[i]], 1);          // deg_out_p
        atomicAdd(&ints[n + dst_p[i]], 1);      // deg_in_p
    } else if (i < 2 * e) {
        int j = i - e;
        atomicAdd(&ints[2 * n + src_s[j]], 1);  // deg_out_s
        atomicAdd(&ints[3 * n + dst_s[j]], 1);  // deg_in_s
    }
}

// one block per relation; 1024 threads; each thread serially scans a run of CH
__global__ void scan_full_kernel(const int* __restrict__ din0, const int* __restrict__ din1,
                                 int* __restrict__ offs, int n) {
    const int CH = 98;                       // 1024*98 >= 100000
    const int* din = blockIdx.x ? din1 : din0;
    int* out = offs + blockIdx.x * NNODES;
    int t = threadIdx.x;
    int base = t * CH;

    int sum = 0;
    for (int k = 0; k < CH; k++) {
        int i = base + k;
        if (i < n) sum += din[i];
    }
    // block exclusive scan of per-thread sums
    int lane = t & 31, wid = t >> 5;
    int incl = sum;
#pragma unroll
    for (int o = 1; o < 32; o <<= 1) {
        int v = __shfl_up_sync(0xffffffffu, incl, o);
        if (lane >= o) incl += v;
    }
    __shared__ int wsum[32];
    if (lane == 31) wsum[wid] = incl;
    __syncthreads();
    if (wid == 0) {
        int v = wsum[lane];
#pragma unroll
        for (int o = 1; o < 32; o <<= 1) {
            int u = __shfl_up_sync(0xffffffffu, v, o);
            if (lane >= o) v += u;
        }
        wsum[lane] = v;
    }
    __syncthreads();
    int pre = (incl - sum) + (wid ? wsum[wid - 1] : 0);   // exclusive prefix for this thread

    int run = pre;
    for (int k = 0; k < CH; k++) {
        int i = base + k;
        if (i < n) {
            out[i] = run;
            run += din[i];
        }
    }
}

// both relations in one launch
__global__ void sort2_kernel(const int* __restrict__ src_p, const int* __restrict__ dst_p,
                             const int* __restrict__ src_s, const int* __restrict__ dst_s,
                             int* __restrict__ ints, const int* __restrict__ offs,
                             int2* __restrict__ edges_p, int2* __restrict__ edges_s,
                             int n, int e) {
    int i = blockIdx.x * blockDim.x + threadIdx.x;
    if (i < e) {
        int s = src_p[i], d = dst_p[i];
        float c = rsqrtf(fmaxf((float)ints[s], 1.0f)) * rsqrtf(fmaxf((float)ints[n + d], 1.0f));
        int slot = offs[d] + atomicAdd(&ints[4 * n + d], 1);
        edges_p[slot] = make_int2(s, __float_as_int(c));
    } else if (i < 2 * e) {
        int j = i - e;
        int s = src_s[j], d = dst_s[j];
        float c = rsqrtf(fmaxf((float)ints[2 * n + s], 1.0f)) * rsqrtf(fmaxf((float)ints[3 * n + d], 1.0f));
        int slot = offs[NNODES + d] + atomicAdd(&ints[5 * n + d], 1);
        edges_s[slot] = make_int2(s, __float_as_int(c));
    }
}

// ---------------- fp32 -> fp16 convert (feat + all 4 weights, one launch) ----
__global__ void convert_all_kernel(const float* __restrict__ x, __half* __restrict__ xh,
                                   const float* __restrict__ w0p, const float* __restrict__ w0s,
                                   const float* __restrict__ w1p, const float* __restrict__ w1s,
                                   __half* __restrict__ wh, int n4x) {
    int i = blockIdx.x * blockDim.x + threadIdx.x;
    if (i < n4x) {
        float4 v = ((const float4*)x)[i];
        __half2 h[2];
        h[0] = __floats2half2_rn(v.x, v.y);
        h[1] = __floats2half2_rn(v.z, v.w);
        ((uint2*)xh)[i] = *(uint2*)h;
    } else {
        int j = i - n4x;                        // [0, 16384): 4 weights x 4096 float4
        if (j < 4 * (HDIM * HDIM / 4)) {
            int wsel = j >> 12, idx = j & 4095;
            const float* w = wsel == 0 ? w0p : wsel == 1 ? w0s : wsel == 2 ? w1p : w1s;
            float4 v = ((const float4*)w)[idx];
            __half2 h[2];
            h[0] = __floats2half2_rn(v.x, v.y);
            h[1] = __floats2half2_rn(v.z, v.w);
            ((uint2*)(wh + (size_t)wsel * HDIM * HDIM))[idx] = *(uint2*)h;
        }
    }
}

// ---------------- HMMA GEMM: both relation weights in one launch -------------
// grid (row_blocks, 2); blockIdx.y selects (W0,Y0) vs (W1,Y1)
__global__ __launch_bounds__(256) void gemm_mma2_kernel(const __half* __restrict__ X,
                                                        const __half* __restrict__ Wa,
                                                        const __half* __restrict__ Wb,
                                                        __half* __restrict__ Ya,
                                                        __half* __restrict__ Yb, int nrows) {
    const __half* W = blockIdx.y ? Wb : Wa;
    __half* Y       = blockIdx.y ? Yb : Ya;

    __shared__ __half Xs[128][40];
    __shared__ __half Ws[32][136];
    const int tid  = threadIdx.x;
    const int warp = tid >> 5, lane = tid & 31;
    const int row0 = blockIdx.x * 128;
    const int wrow = warp * 16;

    float acc[16][4];
#pragma unroll
    for (int t = 0; t < 16; t++)
#pragma unroll
        for (int j = 0; j < 4; j++) acc[t][j] = 0.f;

    for (int k0 = 0; k0 < HDIM; k0 += 32) {
#pragma unroll
        for (int t = tid; t < 512; t += 256) {
            int r = t >> 2, c8 = (t & 3) * 8;
            int gr = row0 + r;
            uint4 v = make_uint4(0u, 0u, 0u, 0u);
            if (gr < nrows) v = *(const uint4*)(X + (size_t)gr * HDIM + k0 + c8);
            *(uint4*)&Xs[r][c8] = v;
        }
#pragma unroll
        for (int t = tid; t < 512; t += 256) {
            int r = t >> 4, c8 = (t & 15) * 8;
            *(uint4*)&Ws[r][c8] = *(const uint4*)(W + (size_t)(k0 + r) * HDIM + c8);
        }
        __syncthreads();

#pragma unroll
        for (int ks = 0; ks < 2; ks++) {
            const int kk = ks * 16;
            uint32_t a[4];
            {
                const __half* pa = &Xs[wrow + (lane & 7) + 8 * ((lane >> 3) & 1)][kk + 8 * (lane >> 4)];
                uint32_t addr = (uint32_t)__cvta_generic_to_shared(pa);
                asm volatile("ldmatrix.sync.aligned.m8n8.x4.shared.b16 {%0,%1,%2,%3}, [%4];"
                             : "=r"(a[0]), "=r"(a[1]), "=r"(a[2]), "=r"(a[3]) : "r"(addr));
            }
#pragma unroll
            for (int nt = 0; nt < 8; nt++) {
                const int n0 = nt * 16;
                uint32_t b[4];
                const __half* pb = &Ws[kk + (lane & 7) + 8 * ((lane >> 3) & 1)][n0 + 8 * (lane >> 4)];
                uint32_t addr = (uint32_t)__cvta_generic_to_shared(pb);
                asm volatile("ldmatrix.sync.aligned.m8n8.x4.trans.shared.b16 {%0,%1,%2,%3}, [%4];"
                             : "=r"(b[0]), "=r"(b[1]), "=r"(b[2]), "=r"(b[3]) : "r"(addr));
                asm volatile("mma.sync.aligned.m16n8k16.row.col.f32.f16.f16.f32 "
                             "{%0,%1,%2,%3}, {%4,%5,%6,%7}, {%8,%9}, {%0,%1,%2,%3};"
                             : "+f"(acc[2 * nt][0]), "+f"(acc[2 * nt][1]),
                               "+f"(acc[2 * nt][2]), "+f"(acc[2 * nt][3])
                             : "r"(a[0]), "r"(a[1]), "r"(a[2]), "r"(a[3]), "r"(b[0]), "r"(b[1]));
                asm volatile("mma.sync.aligned.m16n8k16.row.col.f32.f16.f16.f32 "
                             "{%0,%1,%2,%3}, {%4,%5,%6,%7}, {%8,%9}, {%0,%1,%2,%3};"
                             : "+f"(acc[2 * nt + 1][0]), "+f"(acc[2 * nt + 1][1]),
                               "+f"(acc[2 * nt + 1][2]), "+f"(acc[2 * nt + 1][3])
                             : "r"(a[0]), "r"(a[1]), "r"(a[2]), "r"(a[3]), "r"(b[2]), "r"(b[3]));
            }
        }
        __syncthreads();
    }

    const int rlo = row0 + wrow + (lane >> 2);
    const int rhi = rlo + 8;
    const int cbase = (lane & 3) * 2;
#pragma unroll
    for (int nt = 0; nt < 16; nt++) {
        int c = nt * 8 + cbase;
        if (rlo < nrows)
            *(__half2*)(Y + (size_t)rlo * HDIM + c) = __floats2half2_rn(acc[nt][0], acc[nt][1]);
        if (rhi < nrows)
            *(__half2*)(Y + (size_t)rhi * HDIM + c) = __floats2half2_rn(acc[nt][2], acc[nt][3]);
    }
}

// ---------------- fused aggregate (fp16 gathers, fp32 accum, 4-wide MLP) -----
template <typename OutT>
__global__ void aggregate_kernel(const __half* __restrict__ hp_p, const __half* __restrict__ hp_s,
                                 const int2* __restrict__ ep, const int* __restrict__ offs_p,
                                 const int* __restrict__ deg_p,
                                 const int2* __restrict__ es, const int* __restrict__ offs_s,
                                 const int* __restrict__ deg_s,
                                 const float* __restrict__ bp, const float* __restrict__ bs,
                                 OutT* __restrict__ out, int n) {
    int w = (blockIdx.x * blockDim.x + threadIdx.x) >> 5;
    int lane = threadIdx.x & 31;
    if (w >= n) return;
    float4 v = make_float4(0.f, 0.f, 0.f, 0.f);

#pragma unroll 1
    for (int rel = 0; rel < 2; rel++) {
        const int2* ed = rel ? es : ep;
        const __half* hp = rel ? hp_s : hp_p;
        int st = rel ? offs_s[w] : offs_p[w];
        int en = st + (rel ? deg_s[w] : deg_p[w]);
        int j = st;
        for (; j + 3 < en; j += 4) {
            int2 e0 = __ldg(&ed[j]);
            int2 e1 = __ldg(&ed[j + 1]);
            int2 e2 = __ldg(&ed[j + 2]);
            int2 e3 = __ldg(&ed[j + 3]);
            uint2 r0 = __ldg((const uint2*)(hp + (size_t)e0.x * HDIM) + lane);
            uint2 r1 = __ldg((const uint2*)(hp + (size_t)e1.x * HDIM) + lane);
            uint2 r2 = __ldg((const uint2*)(hp + (size_t)e2.x * HDIM) + lane);
            uint2 r3 = __ldg((const uint2*)(hp + (size_t)e3.x * HDIM) + lane);
            float c0 = __int_as_float(e0.y), c1 = __int_as_float(e1.y);
            float c2 = __int_as_float(e2.y), c3 = __int_as_float(e3.y);
            float2 a0 = __half22float2(*(__half2*)&r0.x), a1 = __half22float2(*(__half2*)&r0.y);
            float2 b0 = __half22float2(*(__half2*)&r1.x), b1 = __half22float2(*(__half2*)&r1.y);
            float2 d0 = __half22float2(*(__half2*)&r2.x), d1 = __half22float2(*(__half2*)&r2.y);
            float2 f0 = __half22float2(*(__half2*)&r3.x), f1 = __half22float2(*(__half2*)&r3.y);
            v.x += c0 * a0.x + c1 * b0.x + c2 * d0.x + c3 * f0.x;
            v.y += c0 * a0.y + c1 * b0.y + c2 * d0.y + c3 * f0.y;
            v.z += c0 * a1.x + c1 * b1.x + c2 * d1.x + c3 * f1.x;
            v.w += c0 * a1.y + c1 * b1.y + c2 * d1.y + c3 * f1.y;
        }
        for (; j < en; j++) {
            int2 e0 = __ldg(&ed[j]);
            uint2 r0 = __ldg((const uint2*)(hp + (size_t)e0.x * HDIM) + lane);
            float c0 = __int_as_float(e0.y);
            float2 a0 = __half22float2(*(__half2*)&r0.x);
            float2 a1 = __half22float2(*(__half2*)&r0.y);
            v.x += c0 * a0.x; v.y += c0 * a0.y; v.z += c0 * a1.x; v.w += c0 * a1.y;
        }
    }
    float4 b1 = ((const float4*)bp)[lane];
    float4 b2 = ((const float4*)bs)[lane];
    float4 r;
    r.x = fmaxf(0.5f * (v.x + b1.x + b2.x), 0.f);
    r.y = fmaxf(0.5f * (v.y + b1.y + b2.y), 0.f);
    r.z = fmaxf(0.5f * (v.z + b1.z + b2.z), 0.f);
    r.w = fmaxf(0.5f * (v.w + b1.w + b2.w), 0.f);
    if (sizeof(OutT) == 4) {
        *((float4*)((float*)out + (size_t)w * HDIM) + lane) = r;
    } else {
        __half2 h[2];
        h[0] = __floats2half2_rn(r.x, r.y);
        h[1] = __floats2half2_rn(r.z, r.w);
        *((uint2*)((__half*)out + (size_t)w * HDIM) + lane) = *(uint2*)h;
    }
}

// ---------------- pair classifier --------------------------------------------
__global__ void pair_kernel(const float* __restrict__ z,
                            const int* __restrict__ ps, const int* __restrict__ pd,
                            const float* __restrict__ Wc, const float* __restrict__ bc,
                            float* __restrict__ out, int p) {
    int w = (blockIdx.x * blockDim.x + threadIdx.x) >> 5;
    int lane = threadIdx.x & 31;
    if (w >= p) return;
    int s = __ldg(&ps[w]), d = __ldg(&pd[w]);
    float4 zs = __ldg((const float4*)(z + (size_t)s * HDIM) + lane);
    float4 zd = __ldg((const float4*)(z + (size_t)d * HDIM) + lane);
    const float4* wc4 = (const float4*)Wc;
    float4 wa = wc4[lane * 2], wb = wc4[lane * 2 + 1];
    float l0 = zs.x * wa.x + zs.y * wa.z + zs.z * wb.x + zs.w * wb.z;
    float l1 = zs.x * wa.y + zs.y * wa.w + zs.z * wb.y + zs.w * wb.w;
    float4 wcv = wc4[64 + lane * 2], wd = wc4[64 + lane * 2 + 1];
    l0 += zd.x * wcv.x + zd.y * wcv.z + zd.z * wd.x + zd.w * wd.z;
    l1 += zd.x * wcv.y + zd.y * wcv.w + zd.z * wd.y + zd.w * wd.w;
#pragma unroll
    for (int o = 16; o; o >>= 1) {
        l0 += __shfl_xor_sync(0xffffffffu, l0, o);
        l1 += __shfl_xor_sync(0xffffffffu, l1, o);
    }
    if (lane == 0) {
        out[(size_t)w * 2] = l0 + bc[0];
        out[(size_t)w * 2 + 1] = l1 + bc[1];
    }
}

// ---------------- launch -----------------------------------------------------

extern "C" void kernel_launch(void* const* d_in, const int* in_sizes, int n_in,
                              void* d_out, int out_size) {
    const float* feat   = (const float*)d_in[0];
    const int* src_ppi  = (const int*)d_in[1];
    const int* dst_ppi  = (const int*)d_in[2];
    const int* src_sim  = (const int*)d_in[3];
    const int* dst_sim  = (const int*)d_in[4];
    const int* pair_src = (const int*)d_in[5];
    const int* pair_dst = (const int*)d_in[6];
    const float* W0_ppi = (const float*)d_in[7];
    const float* b0_ppi = (const float*)d_in[8];
    const float* W0_sim = (const float*)d_in[9];
    const float* b0_sim = (const float*)d_in[10];
    const float* W1_ppi = (const float*)d_in[11];
    const float* b1_ppi = (const float*)d_in[12];
    const float* W1_sim = (const float*)d_in[13];
    const float* b1_sim = (const float*)d_in[14];
    const float* Wc     = (const float*)d_in[15];
    const float* bc     = (const float*)d_in[16];

    const int n = in_sizes[0] / HDIM;
    const int e = in_sizes[1];
    const int p = in_sizes[5];

    float* zout   = (float*)d_out;
    float* logits = (float*)d_out + (size_t)n * HDIM;

    __half *xh, *h16, *hp_ppi, *hp_sim, *wh;
    int *ints, *offs;
    int2 *edges_p, *edges_s;
    cudaGetSymbolAddress((void**)&xh,      g_xh);
    cudaGetSymbolAddress((void**)&h16,     g_h16);
    cudaGetSymbolAddress((void**)&hp_ppi,  g_hp_ppi);
    cudaGetSymbolAddress((void**)&hp_sim,  g_hp_sim);
    cudaGetSymbolAddress((void**)&wh,      g_wh);
    cudaGetSymbolAddress((void**)&ints,    g_ints);
    cudaGetSymbolAddress((void**)&offs,    g_offs);
    cudaGetSymbolAddress((void**)&edges_p, g_edges_p);
    cudaGetSymbolAddress((void**)&edges_s, g_edges_s);

    int* deg_in_p  = ints + n;
    int* deg_in_s  = ints + 3 * n;
    int* offs_p = offs;
    int* offs_s = offs + NNODES;

    __half* w0p = wh;
    __half* w0s = wh + HDIM * HDIM;
    __half* w1p = wh + 2 * HDIM * HDIM;
    __half* w1s = wh + 3 * HDIM * HDIM;

    const int TB = 256;
    const int nh = n * HDIM;
    const int n4x = nh / 4;
    const int e2_blocks   = (2 * e + TB - 1) / TB;
    const int zero_blocks = (6 * n / 4 + TB - 1) / TB;
    const int agg_blocks  = (int)(((long long)n * 32 + TB - 1) / TB);
    const int pair_blocks = (int)(((long long)p * 32 + TB - 1) / TB);
    const int cv_blocks   = (n4x + 4 * (HDIM * HDIM / 4) + TB - 1) / TB;
    dim3 gemm_grid((n + 127) / 128, 2);

    // ---- CSR build (shared by both layers) ----
    zero_i4_kernel<<<zero_blocks, TB>>>((int4*)ints, 6 * n / 4);
    deg2_kernel<<<e2_blocks, TB>>>(src_ppi, dst_ppi, src_sim, dst_sim, ints, n, e);
    scan_full_kernel<<<2, 1024>>>(deg_in_p, deg_in_s, offs, n);
    sort2_kernel<<<e2_blocks, TB>>>(src_ppi, dst_ppi, src_sim, dst_sim, ints, offs,
                                    edges_p, edges_s, n, e);

    // ---- fp16 conversion (feat + weights) ----
    convert_all_kernel<<<cv_blocks, TB>>>(feat, xh, W0_ppi, W0_sim, W1_ppi, W1_sim, wh, n4x);

    // ---- layer 0 ----
    gemm_mma2_kernel<<<gemm_grid, 256>>>(xh, w0p, w0s, hp_ppi, hp_sim, n);
    aggregate_kernel<__half><<<agg_blocks, TB>>>(hp_ppi, hp_sim, edges_p, offs_p, deg_in_p,
                                                 edges_s, offs_s, deg_in_s, b0_ppi, b0_sim, h16, n);

    // ---- layer 1 ----
    gemm_mma2_kernel<<<gemm_grid, 256>>>(h16, w1p, w1s, hp_ppi, hp_sim, n);
    aggregate_kernel<float><<<agg_blocks, TB>>>(hp_ppi, hp_sim, edges_p, offs_p, deg_in_p,
                                                edges_s, offs_s, deg_in_s, b1_ppi, b1_sim, zout, n);

    // ---- pair classifier ----
    pair_kernel<<<pair_blocks, TB>>>(zout, pair_src, pair_dst, Wc, bc, logits, p);
}